// round 6
// baseline (speedup 1.0000x reference)
#include <cuda_runtime.h>

#define NN 50000
#define NE 800000
#define IN_CH 512
#define HID 256
#define OUTC 128

// ---- scratch (static device globals; no allocations allowed) ----
__device__ float g_dinv[NN];
__device__ int   g_cnt[NN];                      // in-degree (excl. self)
__device__ int   g_rowptr[NN + 1];
__device__ int   g_cursor[NN];
__device__ int   g_esrc[NE];                     // src ids sorted by dst
__device__ float g_h1[(size_t)NN * HID];         // x @ W1
__device__ float g_agg1[(size_t)NN * HID];       // aggregated + relu
__device__ float g_h2[(size_t)NN * OUTC];        // agg1 @ W2
__device__ int   g_is64;                         // edge_index dtype flag

// ---------------------------------------------------------------------------
// dtype detection: int64 ids (< 2^31) have all-zero odd 32-bit words.
// ---------------------------------------------------------------------------
__global__ void k_flag_init() { g_is64 = 1; }

__global__ void k_detect(const unsigned int* __restrict__ w) {
    unsigned acc = 0;
    for (int i = threadIdx.x; i < 2048; i += blockDim.x) acc |= w[2 * i + 1];
    if (acc) g_is64 = 0;
}

__device__ __forceinline__ int edge_idx(const void* ei, size_t pos, int is64) {
    int i = is64 ? (int)((const long long*)ei)[pos] : ((const int*)ei)[pos];
    i = i < 0 ? 0 : (i >= NN ? NN - 1 : i);      // clamp: trap insurance
    return i;
}

// ---------------------------------------------------------------------------
// CSR build
// ---------------------------------------------------------------------------
__global__ void k_zero_cnt() {
    int i = blockIdx.x * blockDim.x + threadIdx.x;
    if (i < NN) g_cnt[i] = 0;
}

__global__ void k_count(const void* __restrict__ ei) {
    int e = blockIdx.x * blockDim.x + threadIdx.x;
    if (e >= NE) return;
    atomicAdd(&g_cnt[edge_idx(ei, (size_t)NE + e, g_is64)], 1);
}

__global__ void k_dinv_from_cnt() {
    int i = blockIdx.x * blockDim.x + threadIdx.x;
    if (i < NN) g_dinv[i] = rsqrtf((float)g_cnt[i] + 1.0f);  // +1 self-loop
}

// single-block exclusive scan of g_cnt -> g_rowptr / g_cursor
__global__ void k_scan() {
    __shared__ int s[1024];
    const int t  = threadIdx.x;
    const int CH = (NN + 1023) / 1024;           // 49
    const int base = t * CH;
    int sum = 0;
    for (int i = 0; i < CH; i++) {
        int idx = base + i;
        sum += (idx < NN) ? g_cnt[idx] : 0;
    }
    s[t] = sum;
    __syncthreads();
    for (int off = 1; off < 1024; off <<= 1) {   // Hillis-Steele inclusive
        int v = (t >= off) ? s[t - off] : 0;
        __syncthreads();
        s[t] += v;
        __syncthreads();
    }
    int run = (t == 0) ? 0 : s[t - 1];
    for (int i = 0; i < CH; i++) {
        int idx = base + i;
        if (idx < NN) {
            g_rowptr[idx] = run;
            g_cursor[idx] = run;
            run += g_cnt[idx];
        }
    }
    if (t == 1023) g_rowptr[NN] = s[1023];
}

__global__ void k_fill(const void* __restrict__ ei) {
    int e = blockIdx.x * blockDim.x + threadIdx.x;
    if (e >= NE) return;
    int is64 = g_is64;
    int s = edge_idx(ei, (size_t)e, is64);
    int d = edge_idx(ei, (size_t)NE + e, is64);
    int pos = atomicAdd(&g_cursor[d], 1);
    g_esrc[pos] = s;
}

// ---------------------------------------------------------------------------
// SGEMM: C[M,N] = A[M,K] @ B[K,N], fp32, 128x128x16 tile, 8x8 per thread
// ---------------------------------------------------------------------------
__global__ __launch_bounds__(256, 2)
void sgemm_128x128(const float* __restrict__ A, const float* __restrict__ B,
                   float* __restrict__ C, int M, int N, int K) {
    __shared__ float As[16][129];
    __shared__ __align__(16) float Bs[16][128];

    const int tid  = threadIdx.x;
    const int brow = blockIdx.x * 128;
    const int bcol = blockIdx.y * 128;
    const int trow = (tid >> 4) * 8;
    const int tcol = (tid & 15) * 8;

    float acc[8][8];
#pragma unroll
    for (int i = 0; i < 8; i++)
#pragma unroll
        for (int j = 0; j < 8; j++) acc[i][j] = 0.0f;

    for (int k0 = 0; k0 < K; k0 += 16) {
#pragma unroll
        for (int i = 0; i < 2; i++) {
            int idx = i * 256 + tid;
            int row = idx >> 2;
            int c4  = idx & 3;
            float4 v = make_float4(0.f, 0.f, 0.f, 0.f);
            if (brow + row < M)
                v = *(const float4*)(A + (size_t)(brow + row) * K + k0 + c4 * 4);
            As[c4 * 4 + 0][row] = v.x;
            As[c4 * 4 + 1][row] = v.y;
            As[c4 * 4 + 2][row] = v.z;
            As[c4 * 4 + 3][row] = v.w;
        }
#pragma unroll
        for (int i = 0; i < 2; i++) {
            int idx = i * 256 + tid;
            int row = idx >> 5;
            int c4  = idx & 31;
            float4 v = *(const float4*)(B + (size_t)(k0 + row) * N + bcol + c4 * 4);
            *(float4*)&Bs[row][c4 * 4] = v;
        }
        __syncthreads();

#pragma unroll
        for (int kk = 0; kk < 16; kk++) {
            float a[8], b[8];
#pragma unroll
            for (int i = 0; i < 8; i++) a[i] = As[kk][trow + i];
            *(float4*)&b[0] = *(const float4*)&Bs[kk][tcol];
            *(float4*)&b[4] = *(const float4*)&Bs[kk][tcol + 4];
#pragma unroll
            for (int i = 0; i < 8; i++)
#pragma unroll
                for (int j = 0; j < 8; j++)
                    acc[i][j] = fmaf(a[i], b[j], acc[i][j]);
        }
        __syncthreads();
    }

#pragma unroll
    for (int i = 0; i < 8; i++) {
        int row = brow + trow + i;
        if (row < M) {
#pragma unroll
            for (int j = 0; j < 8; j += 4) {
                float4 v = make_float4(acc[i][j], acc[i][j + 1],
                                       acc[i][j + 2], acc[i][j + 3]);
                *(float4*)(C + (size_t)row * N + bcol + tcol + j) = v;
            }
        }
    }
}

// ---------------------------------------------------------------------------
// fused CSR gather: out[d,:] = relu?( dinv[d]^2 * h[d,:]
//                              + sum_e dinv[src]*dinv[d] * h[src,:] + bias )
// C = feature width, L = C/4 lanes per node, 256/L nodes per block
// ---------------------------------------------------------------------------
template <int C, bool RELU>
__global__ __launch_bounds__(256)
void k_gather(const float* __restrict__ h,
              const float* __restrict__ bias,
              float* __restrict__ out) {
    constexpr int L   = C / 4;
    constexpr int NPB = 256 / L;
    int node = blockIdx.x * NPB + threadIdx.x / L;
    if (node >= NN) return;
    int lane = threadIdx.x % L;

    const float4* h4 = (const float4*)h;
    float dd = g_dinv[node];

    float4 self = h4[(size_t)node * L + lane];
    float wself = dd * dd;
    float4 acc;
    acc.x = self.x * wself; acc.y = self.y * wself;
    acc.z = self.z * wself; acc.w = self.w * wself;

    int beg = g_rowptr[node];
    int end = g_rowptr[node + 1];
    for (int e = beg; e < end; e++) {
        int s   = __ldg(&g_esrc[e]);
        float w = __ldg(&g_dinv[s]) * dd;
        float4 v = h4[(size_t)s * L + lane];
        acc.x = fmaf(v.x, w, acc.x);
        acc.y = fmaf(v.y, w, acc.y);
        acc.z = fmaf(v.z, w, acc.z);
        acc.w = fmaf(v.w, w, acc.w);
    }

    float4 b = ((const float4*)bias)[lane];
    acc.x += b.x; acc.y += b.y; acc.z += b.z; acc.w += b.w;
    if (RELU) {
        acc.x = fmaxf(acc.x, 0.f); acc.y = fmaxf(acc.y, 0.f);
        acc.z = fmaxf(acc.z, 0.f); acc.w = fmaxf(acc.w, 0.f);
    }
    ((float4*)out)[(size_t)node * L + lane] = acc;
}

// ---------------------------------------------------------------------------
extern "C" void kernel_launch(void* const* d_in, const int* in_sizes, int n_in,
                              void* d_out, int out_size) {
    const float* x  = (const float*)d_in[0];
    const void*  ei = d_in[1];
    const float* W1 = (const float*)d_in[2];
    const float* b1 = (const float*)d_in[3];
    const float* W2 = (const float*)d_in[4];
    const float* b2 = (const float*)d_in[5];
    float*       out = (float*)d_out;

    float *h1, *agg1, *h2;
    cudaGetSymbolAddress((void**)&h1,   g_h1);
    cudaGetSymbolAddress((void**)&agg1, g_agg1);
    cudaGetSymbolAddress((void**)&h2,   g_h2);

    // dtype detection + CSR build
    k_flag_init<<<1, 1>>>();
    k_detect   <<<1, 256>>>((const unsigned int*)ei);
    k_zero_cnt <<<(NN + 255) / 256, 256>>>();
    k_count    <<<(NE + 255) / 256, 256>>>(ei);
    k_dinv_from_cnt<<<(NN + 255) / 256, 256>>>();
    k_scan     <<<1, 1024>>>();
    k_fill     <<<(NE + 255) / 256, 256>>>(ei);

    // ---- layer 1: GEMM + fused gather/bias/relu ----
    dim3 g1((NN + 127) / 128, HID / 128);
    sgemm_128x128<<<g1, 256>>>(x, W1, h1, NN, HID, IN_CH);
    k_gather<HID, true><<<(NN + 3) / 4, 256>>>(h1, b1, agg1);

    // ---- layer 2: GEMM + fused gather/bias ----
    dim3 g2((NN + 127) / 128, OUTC / 128);
    sgemm_128x128<<<g2, 256>>>(agg1, W2, h2, NN, OUTC, HID);
    k_gather<OUTC, false><<<(NN + 7) / 8, 256>>>(h2, b2, out);
}

// round 9
// speedup vs baseline: 1.4294x; 1.4294x over previous
#include <cuda_runtime.h>
#include <cuda_bf16.h>
#include <cstdint>

#define NN 50000
#define NE 800000
#define IN_CH 512
#define HID 256
#define OUTC 128

// ---- scratch (static device globals; no allocations allowed) ----
__device__ float g_dinv[NN];
__device__ int   g_cnt[NN];
__device__ int   g_rowptr[NN + 1];
__device__ int   g_cursor[NN];
__device__ int   g_esrc[NE];
__device__ float g_h1[(size_t)NN * HID];          // layer1 GEMM out (fp32)
__device__ float g_h2[(size_t)NN * OUTC];         // layer2 GEMM out (fp32)
__device__ int   g_is64;

// bf16 hi/lo split operands
__device__ __nv_bfloat16 g_xhi[(size_t)NN * IN_CH];
__device__ __nv_bfloat16 g_xlo[(size_t)NN * IN_CH];
__device__ __nv_bfloat16 g_aghi[(size_t)NN * HID];
__device__ __nv_bfloat16 g_aglo[(size_t)NN * HID];
__device__ __nv_bfloat16 g_w1hi[HID * IN_CH];     // transposed [N][K]
__device__ __nv_bfloat16 g_w1lo[HID * IN_CH];
__device__ __nv_bfloat16 g_w2hi[OUTC * HID];
__device__ __nv_bfloat16 g_w2lo[OUTC * HID];

// ============================ helpers ============================
__device__ __forceinline__ uint32_t smem_u32(const void* p) {
    uint32_t a;
    asm("{ .reg .u64 t; cvta.to.shared.u64 t, %1; cvt.u32.u64 %0, t; }" : "=r"(a) : "l"(p));
    return a;
}

__device__ __forceinline__ void ldmx4(uint32_t* r, uint32_t addr) {
    asm volatile("ldmatrix.sync.aligned.m8n8.x4.shared.b16 {%0,%1,%2,%3}, [%4];"
        : "=r"(r[0]), "=r"(r[1]), "=r"(r[2]), "=r"(r[3]) : "r"(addr));
}

__device__ __forceinline__ void mma16816(float* c, const uint32_t* a,
                                         uint32_t b0, uint32_t b1) {
    asm volatile("mma.sync.aligned.m16n8k16.row.col.f32.bf16.bf16.f32 "
        "{%0,%1,%2,%3}, {%4,%5,%6,%7}, {%8,%9}, {%0,%1,%2,%3};"
        : "+f"(c[0]), "+f"(c[1]), "+f"(c[2]), "+f"(c[3])
        : "r"(a[0]), "r"(a[1]), "r"(a[2]), "r"(a[3]), "r"(b0), "r"(b1));
}

// ============================ dtype detect ============================
__global__ void k_flag_init() { g_is64 = 1; }
__global__ void k_detect(const unsigned int* __restrict__ w) {
    unsigned acc = 0;
    for (int i = threadIdx.x; i < 2048; i += blockDim.x) acc |= w[2 * i + 1];
    if (acc) g_is64 = 0;
}
__device__ __forceinline__ int edge_idx(const void* ei, size_t pos, int is64) {
    int i = is64 ? (int)((const long long*)ei)[pos] : ((const int*)ei)[pos];
    return i < 0 ? 0 : (i >= NN ? NN - 1 : i);
}

// ============================ CSR build ============================
__global__ void k_zero_cnt() {
    int i = blockIdx.x * blockDim.x + threadIdx.x;
    if (i < NN) g_cnt[i] = 0;
}
__global__ void k_count(const void* __restrict__ ei) {
    int e = blockIdx.x * blockDim.x + threadIdx.x;
    if (e < NE) atomicAdd(&g_cnt[edge_idx(ei, (size_t)NE + e, g_is64)], 1);
}
__global__ void k_dinv_from_cnt() {
    int i = blockIdx.x * blockDim.x + threadIdx.x;
    if (i < NN) g_dinv[i] = rsqrtf((float)g_cnt[i] + 1.0f);
}
__global__ void k_scan() {
    __shared__ int s[1024];
    const int t = threadIdx.x;
    const int CH = (NN + 1023) / 1024;
    const int base = t * CH;
    int sum = 0;
    for (int i = 0; i < CH; i++) { int idx = base + i; sum += (idx < NN) ? g_cnt[idx] : 0; }
    s[t] = sum;
    __syncthreads();
    for (int off = 1; off < 1024; off <<= 1) {
        int v = (t >= off) ? s[t - off] : 0;
        __syncthreads(); s[t] += v; __syncthreads();
    }
    int run = (t == 0) ? 0 : s[t - 1];
    for (int i = 0; i < CH; i++) {
        int idx = base + i;
        if (idx < NN) { g_rowptr[idx] = run; g_cursor[idx] = run; run += g_cnt[idx]; }
    }
    if (t == 1023) g_rowptr[NN] = s[1023];
}
__global__ void k_fill(const void* __restrict__ ei) {
    int e = blockIdx.x * blockDim.x + threadIdx.x;
    if (e >= NE) return;
    int is64 = g_is64;
    int s = edge_idx(ei, (size_t)e, is64);
    int d = edge_idx(ei, (size_t)NE + e, is64);
    g_esrc[atomicAdd(&g_cursor[d], 1)] = s;
}

// ============================ bf16 split converters ============================
__global__ void k_split(const float* __restrict__ in, __nv_bfloat16* __restrict__ hi,
                        __nv_bfloat16* __restrict__ lo, int n4) {
    int i = blockIdx.x * blockDim.x + threadIdx.x;
    if (i >= n4) return;
    float4 v = ((const float4*)in)[i];
    __nv_bfloat16 hx = __float2bfloat16(v.x), hy = __float2bfloat16(v.y);
    __nv_bfloat16 hz = __float2bfloat16(v.z), hw = __float2bfloat16(v.w);
    ((__nv_bfloat162*)hi)[2 * i]     = __nv_bfloat162{hx, hy};
    ((__nv_bfloat162*)hi)[2 * i + 1] = __nv_bfloat162{hz, hw};
    ((__nv_bfloat162*)lo)[2 * i] = __nv_bfloat162{
        __float2bfloat16(v.x - __bfloat162float(hx)),
        __float2bfloat16(v.y - __bfloat162float(hy))};
    ((__nv_bfloat162*)lo)[2 * i + 1] = __nv_bfloat162{
        __float2bfloat16(v.z - __bfloat162float(hz)),
        __float2bfloat16(v.w - __bfloat162float(hw))};
}

// W [K,N] row-major -> Wt hi/lo [N][K]
__global__ void k_splitT(const float* __restrict__ W, __nv_bfloat16* __restrict__ hi,
                         __nv_bfloat16* __restrict__ lo, int K, int N) {
    int idx = blockIdx.x * blockDim.x + threadIdx.x;
    if (idx >= K * N) return;
    int k = idx / N, n = idx - k * N;
    float v = W[idx];
    __nv_bfloat16 h = __float2bfloat16(v);
    hi[(size_t)n * K + k] = h;
    lo[(size_t)n * K + k] = __float2bfloat16(v - __bfloat162float(h));
}

// ============================ HMMA GEMM (mma.sync bf16, hi/lo split) ==========
// C[M,NT] = A[M,K] @ Bt[NT,K]^T.  CTA tile 128x128, 8 warps (2m x 4n),
// warp tile 64x32, BK=32. smem padded stride 40 bf16 (conflict-free ldmatrix).
template <int K, int NT>
__global__ __launch_bounds__(256)
void k_mma(const __nv_bfloat16* __restrict__ Ahi, const __nv_bfloat16* __restrict__ Alo,
           const __nv_bfloat16* __restrict__ Bhi, const __nv_bfloat16* __restrict__ Blo,
           float* __restrict__ C) {
    constexpr int ST = 40;                      // smem row stride in bf16
    __shared__ __align__(16) __nv_bfloat16 s[4][128 * ST];  // Ahi, Alo, Bhi, Blo

    const int tid  = threadIdx.x;
    const int lane = tid & 31;
    const int wid  = tid >> 5;
    const int wm   = (wid & 1) * 64;
    const int wn   = (wid >> 1) * 32;
    const int m0   = blockIdx.x * 128;
    const int n0   = blockIdx.y * 128;

    float acc[4][4][4];
#pragma unroll
    for (int mt = 0; mt < 4; mt++)
#pragma unroll
        for (int nt = 0; nt < 4; nt++)
#pragma unroll
            for (int j = 0; j < 4; j++) acc[mt][nt][j] = 0.0f;

    // ldmatrix smem addresses (constant across chunks except ks offset)
    const int a_row = wm + (lane & 15);
    const int a_kof = ((lane >> 4) & 1) << 3;
    const int b_row = wn + (lane & 7) + (((lane >> 4) & 1) << 3);
    const int b_kof = ((lane >> 3) & 1) << 3;

    for (int kc0 = 0; kc0 < K; kc0 += 32) {
        // ---- load 4 tiles: 128 rows x 4 float4 each ----
#pragma unroll
        for (int it = 0; it < 8; it++) {
            int j   = it * 256 + tid;           // 0..2047
            int buf = j >> 9;
            int r   = (j >> 2) & 127;
            int c   = j & 3;
            const __nv_bfloat16* base =
                (buf == 0) ? Ahi : (buf == 1) ? Alo : (buf == 2) ? Bhi : Blo;
            int grow = (buf < 2) ? (m0 + r) : (n0 + r);
            float4 v = make_float4(0.f, 0.f, 0.f, 0.f);
            if (buf >= 2 || grow < NN)
                v = ((const float4*)(base + (size_t)grow * K + kc0))[c];
            *(float4*)&s[buf][r * ST + c * 8] = v;
        }
        __syncthreads();

#pragma unroll
        for (int ks = 0; ks < 2; ks++) {
            uint32_t ah[4][4], al[4][4], bh[2][4], bl[2][4];
#pragma unroll
            for (int mt = 0; mt < 4; mt++) {
                uint32_t off = ((a_row + mt * 16) * ST + ks * 16 + a_kof) * 2;
                ldmx4(ah[mt], smem_u32(&s[0][0]) + off);
                ldmx4(al[mt], smem_u32(&s[1][0]) + off);
            }
#pragma unroll
            for (int p = 0; p < 2; p++) {
                uint32_t off = ((b_row + p * 16) * ST + ks * 16 + b_kof) * 2;
                ldmx4(bh[p], smem_u32(&s[2][0]) + off);
                ldmx4(bl[p], smem_u32(&s[3][0]) + off);
            }
#pragma unroll
            for (int mt = 0; mt < 4; mt++)
#pragma unroll
                for (int nt = 0; nt < 4; nt++) {
                    int p = nt >> 1, q = (nt & 1) * 2;
                    mma16816(acc[mt][nt], ah[mt], bh[p][q], bh[p][q + 1]);
                    mma16816(acc[mt][nt], ah[mt], bl[p][q], bl[p][q + 1]);
                    mma16816(acc[mt][nt], al[mt], bh[p][q], bh[p][q + 1]);
                }
        }
        __syncthreads();
    }

    // ---- epilogue: fragment -> fp32 C ----
#pragma unroll
    for (int mt = 0; mt < 4; mt++) {
        int row0 = m0 + wm + mt * 16 + (lane >> 2);
        int row1 = row0 + 8;
#pragma unroll
        for (int nt = 0; nt < 4; nt++) {
            int col = n0 + wn + nt * 8 + (lane & 3) * 2;
            if (row0 < NN)
                *(float2*)(C + (size_t)row0 * NT + col) =
                    make_float2(acc[mt][nt][0], acc[mt][nt][1]);
            if (row1 < NN)
                *(float2*)(C + (size_t)row1 * NT + col) =
                    make_float2(acc[mt][nt][2], acc[mt][nt][3]);
        }
    }
}

// ============================ fused CSR gather ============================
template <int C, bool SPLIT>
__global__ __launch_bounds__(256)
void k_gather(const float* __restrict__ h, const float* __restrict__ bias,
              float* __restrict__ outf, __nv_bfloat16* __restrict__ outhi,
              __nv_bfloat16* __restrict__ outlo) {
    constexpr int L = C / 4;
    constexpr int NPB = 256 / L;
    int node = blockIdx.x * NPB + threadIdx.x / L;
    if (node >= NN) return;
    int lane = threadIdx.x % L;

    const float4* h4 = (const float4*)h;
    float dd = g_dinv[node];
    float4 self = h4[(size_t)node * L + lane];
    float ws = dd * dd;
    float4 acc = make_float4(self.x * ws, self.y * ws, self.z * ws, self.w * ws);

    int beg = g_rowptr[node], end = g_rowptr[node + 1];
    for (int e = beg; e < end; e++) {
        int s = __ldg(&g_esrc[e]);
        float w = __ldg(&g_dinv[s]) * dd;
        float4 v = h4[(size_t)s * L + lane];
        acc.x = fmaf(v.x, w, acc.x);
        acc.y = fmaf(v.y, w, acc.y);
        acc.z = fmaf(v.z, w, acc.z);
        acc.w = fmaf(v.w, w, acc.w);
    }
    float4 b = ((const float4*)bias)[lane];
    acc.x += b.x; acc.y += b.y; acc.z += b.z; acc.w += b.w;

    if (SPLIT) {
        acc.x = fmaxf(acc.x, 0.f); acc.y = fmaxf(acc.y, 0.f);
        acc.z = fmaxf(acc.z, 0.f); acc.w = fmaxf(acc.w, 0.f);
        __nv_bfloat16 hx = __float2bfloat16(acc.x), hy = __float2bfloat16(acc.y);
        __nv_bfloat16 hz = __float2bfloat16(acc.z), hw = __float2bfloat16(acc.w);
        size_t p2 = ((size_t)node * L + lane) * 2;
        ((__nv_bfloat162*)outhi)[p2]     = __nv_bfloat162{hx, hy};
        ((__nv_bfloat162*)outhi)[p2 + 1] = __nv_bfloat162{hz, hw};
        ((__nv_bfloat162*)outlo)[p2] = __nv_bfloat162{
            __float2bfloat16(acc.x - __bfloat162float(hx)),
            __float2bfloat16(acc.y - __bfloat162float(hy))};
        ((__nv_bfloat162*)outlo)[p2 + 1] = __nv_bfloat162{
            __float2bfloat16(acc.z - __bfloat162float(hz)),
            __float2bfloat16(acc.w - __bfloat162float(hw))};
    } else {
        ((float4*)outf)[(size_t)node * L + lane] = acc;
    }
}

// ============================ launch ============================
extern "C" void kernel_launch(void* const* d_in, const int* in_sizes, int n_in,
                              void* d_out, int out_size) {
    const float* x  = (const float*)d_in[0];
    const void*  ei = d_in[1];
    const float* W1 = (const float*)d_in[2];
    const float* b1 = (const float*)d_in[3];
    const float* W2 = (const float*)d_in[4];
    const float* b2 = (const float*)d_in[5];
    float*       out = (float*)d_out;

    float *h1, *h2;
    __nv_bfloat16 *xhi, *xlo, *aghi, *aglo, *w1hi, *w1lo, *w2hi, *w2lo;
    cudaGetSymbolAddress((void**)&h1, g_h1);
    cudaGetSymbolAddress((void**)&h2, g_h2);
    cudaGetSymbolAddress((void**)&xhi, g_xhi);
    cudaGetSymbolAddress((void**)&xlo, g_xlo);
    cudaGetSymbolAddress((void**)&aghi, g_aghi);
    cudaGetSymbolAddress((void**)&aglo, g_aglo);
    cudaGetSymbolAddress((void**)&w1hi, g_w1hi);
    cudaGetSymbolAddress((void**)&w1lo, g_w1lo);
    cudaGetSymbolAddress((void**)&w2hi, g_w2hi);
    cudaGetSymbolAddress((void**)&w2lo, g_w2lo);

    // dtype + CSR
    k_flag_init<<<1, 1>>>();
    k_detect<<<1, 256>>>((const unsigned int*)ei);
    k_zero_cnt<<<(NN + 255) / 256, 256>>>();
    k_count<<<(NE + 255) / 256, 256>>>(ei);
    k_dinv_from_cnt<<<(NN + 255) / 256, 256>>>();
    k_scan<<<1, 1024>>>();
    k_fill<<<(NE + 255) / 256, 256>>>(ei);

    // operand splits
    k_split<<<((size_t)NN * IN_CH / 4 + 255) / 256, 256>>>(x, xhi, xlo, NN * IN_CH / 4);
    k_splitT<<<(IN_CH * HID + 255) / 256, 256>>>(W1, w1hi, w1lo, IN_CH, HID);
    k_splitT<<<(HID * OUTC + 255) / 256, 256>>>(W2, w2hi, w2lo, HID, OUTC);

    const int NB = (NN + 127) / 128;   // 391

    // ---- layer 1 ----
    dim3 g1(NB, HID / 128);
    k_mma<IN_CH, HID><<<g1, 256>>>(xhi, xlo, w1hi, w1lo, h1);
    k_gather<HID, true><<<(NN + 3) / 4, 256>>>(h1, b1, nullptr, aghi, aglo);

    // ---- layer 2 ----
    dim3 g2(NB, OUTC / 128);
    k_mma<HID, OUTC><<<g2, 256>>>(aghi, aglo, w2hi, w2lo, h2);
    k_gather<OUTC, false><<<(NN + 7) / 8, 256>>>(h2, b2, out, nullptr, nullptr);
}

// round 10
// speedup vs baseline: 1.5485x; 1.0833x over previous
#include <cuda_runtime.h>
#include <cuda_bf16.h>
#include <cstdint>

#define NN 50000
#define NE 800000
#define IN_CH 512
#define HID 256
#define OUTC 128

// ---- scratch (static device globals; no allocations allowed) ----
__device__ float g_dinv[NN];
__device__ int   g_cnt[NN];
__device__ int   g_rowptr[NN + 1];
__device__ int   g_cursor[NN];
__device__ int   g_esrc[NE];
__device__ float g_h1[(size_t)NN * HID];
__device__ float g_h2[(size_t)NN * OUTC];
__device__ int   g_is64;

__device__ __nv_bfloat16 g_aghi[(size_t)NN * HID];
__device__ __nv_bfloat16 g_aglo[(size_t)NN * HID];
__device__ __nv_bfloat16 g_w1hi[HID * IN_CH];     // transposed [N][K]
__device__ __nv_bfloat16 g_w1lo[HID * IN_CH];
__device__ __nv_bfloat16 g_w2hi[OUTC * HID];
__device__ __nv_bfloat16 g_w2lo[OUTC * HID];

// ============================ helpers ============================
__device__ __forceinline__ uint32_t smem_u32(const void* p) {
    uint32_t a;
    asm("{ .reg .u64 t; cvta.to.shared.u64 t, %1; cvt.u32.u64 %0, t; }" : "=r"(a) : "l"(p));
    return a;
}
__device__ __forceinline__ void ldmx4(uint32_t* r, uint32_t addr) {
    asm volatile("ldmatrix.sync.aligned.m8n8.x4.shared.b16 {%0,%1,%2,%3}, [%4];"
        : "=r"(r[0]), "=r"(r[1]), "=r"(r[2]), "=r"(r[3]) : "r"(addr));
}
__device__ __forceinline__ void mma16816(float* c, const uint32_t* a,
                                         uint32_t b0, uint32_t b1) {
    asm volatile("mma.sync.aligned.m16n8k16.row.col.f32.bf16.bf16.f32 "
        "{%0,%1,%2,%3}, {%4,%5,%6,%7}, {%8,%9}, {%0,%1,%2,%3};"
        : "+f"(c[0]), "+f"(c[1]), "+f"(c[2]), "+f"(c[3])
        : "r"(a[0]), "r"(a[1]), "r"(a[2]), "r"(a[3]), "r"(b0), "r"(b1));
}

// ============================ dtype detect ============================
__global__ void k_flag_init() { g_is64 = 1; }
__global__ void k_detect(const unsigned int* __restrict__ w) {
    unsigned acc = 0;
    for (int i = threadIdx.x; i < 2048; i += blockDim.x) acc |= w[2 * i + 1];
    if (acc) g_is64 = 0;
}
__device__ __forceinline__ int edge_idx(const void* ei, size_t pos, int is64) {
    int i = is64 ? (int)((const long long*)ei)[pos] : ((const int*)ei)[pos];
    return i < 0 ? 0 : (i >= NN ? NN - 1 : i);
}

// ============================ CSR build ============================
__global__ void k_zero_cnt() {
    int i = blockIdx.x * blockDim.x + threadIdx.x;
    if (i < NN) g_cnt[i] = 0;
}
__global__ void k_count(const void* __restrict__ ei) {
    int e = blockIdx.x * blockDim.x + threadIdx.x;
    if (e < NE) atomicAdd(&g_cnt[edge_idx(ei, (size_t)NE + e, g_is64)], 1);
}
__global__ void k_dinv_from_cnt() {
    int i = blockIdx.x * blockDim.x + threadIdx.x;
    if (i < NN) g_dinv[i] = rsqrtf((float)g_cnt[i] + 1.0f);
}
__global__ void k_scan() {
    __shared__ int s[1024];
    const int t = threadIdx.x;
    const int CH = (NN + 1023) / 1024;
    const int base = t * CH;
    int sum = 0;
    for (int i = 0; i < CH; i++) { int idx = base + i; sum += (idx < NN) ? g_cnt[idx] : 0; }
    s[t] = sum;
    __syncthreads();
    for (int off = 1; off < 1024; off <<= 1) {
        int v = (t >= off) ? s[t - off] : 0;
        __syncthreads(); s[t] += v; __syncthreads();
    }
    int run = (t == 0) ? 0 : s[t - 1];
    for (int i = 0; i < CH; i++) {
        int idx = base + i;
        if (idx < NN) { g_rowptr[idx] = run; g_cursor[idx] = run; run += g_cnt[idx]; }
    }
    if (t == 1023) g_rowptr[NN] = s[1023];
}
__global__ void k_fill(const void* __restrict__ ei) {
    int e = blockIdx.x * blockDim.x + threadIdx.x;
    if (e >= NE) return;
    int is64 = g_is64;
    int s = edge_idx(ei, (size_t)e, is64);
    int d = edge_idx(ei, (size_t)NE + e, is64);
    g_esrc[atomicAdd(&g_cursor[d], 1)] = s;
}

// ============================ weight split (transposed) ============================
__global__ void k_splitT(const float* __restrict__ W, __nv_bfloat16* __restrict__ hi,
                         __nv_bfloat16* __restrict__ lo, int K, int N) {
    int idx = blockIdx.x * blockDim.x + threadIdx.x;
    if (idx >= K * N) return;
    int k = idx / N, n = idx - k * N;
    float v = W[idx];
    __nv_bfloat16 h = __float2bfloat16(v);
    hi[(size_t)n * K + k] = h;
    lo[(size_t)n * K + k] = __float2bfloat16(v - __bfloat162float(h));
}

// ============================ HMMA GEMM (bf16 hi/lo split, pipelined) =========
// C[M,NT] = A[M,K] @ Bt[NT,K]^T.  CTA tile 128x128, 8 warps (2m x 4n),
// warp tile 64x32, BK=32.  Register-prefetch software pipeline.
// AFP32: A is fp32, split to hi/lo in registers at smem-store time.
template <int K, int NT, bool AFP32>
__global__ __launch_bounds__(256)
void k_mma(const float* __restrict__ A32,
           const __nv_bfloat16* __restrict__ Ahi, const __nv_bfloat16* __restrict__ Alo,
           const __nv_bfloat16* __restrict__ Bhi, const __nv_bfloat16* __restrict__ Blo,
           float* __restrict__ C) {
    constexpr int ST = 40;
    constexpr int CHUNKS = K / 32;
    __shared__ __align__(16) __nv_bfloat16 s[4][128 * ST];  // Ahi, Alo, Bhi, Blo

    const int tid  = threadIdx.x;
    const int lane = tid & 31;
    const int wid  = tid >> 5;
    const int wm   = (wid & 1) * 64;
    const int wn   = (wid >> 1) * 32;
    const int m0   = blockIdx.x * 128;
    const int n0   = blockIdx.y * 128;

    float acc[4][4][4];
#pragma unroll
    for (int mt = 0; mt < 4; mt++)
#pragma unroll
        for (int nt = 0; nt < 4; nt++)
#pragma unroll
            for (int j = 0; j < 4; j++) acc[mt][nt][j] = 0.0f;

    const int a_row = wm + (lane & 15);
    const int a_kof = ((lane >> 4) & 1) << 3;
    const int b_row = wn + (lane & 7) + (((lane >> 4) & 1) << 3);
    const int b_kof = ((lane >> 3) & 1) << 3;

    float4 pa[4];   // AFP32: 4 fp32 float4 ; else [0..1]=Ahi, [2..3]=Alo
    float4 pb[4];   // [0..1]=Bhi, [2..3]=Blo

    // ---- prefetch loaders ----
    auto load_chunk = [&](int kc0) {
        if (AFP32) {
#pragma unroll
            for (int it = 0; it < 4; it++) {
                int idx = it * 256 + tid;
                int r = idx >> 3, c = idx & 7;
                int row = m0 + r;
                pa[it] = (row < NN)
                    ? ((const float4*)(A32 + (size_t)row * K + kc0))[c]
                    : make_float4(0.f, 0.f, 0.f, 0.f);
            }
        } else {
#pragma unroll
            for (int it = 0; it < 2; it++) {
                int idx = it * 256 + tid;
                int r = idx >> 2, c = idx & 3;
                int row = m0 + r;
                if (row < NN) {
                    pa[it]     = ((const float4*)(Ahi + (size_t)row * K + kc0))[c];
                    pa[2 + it] = ((const float4*)(Alo + (size_t)row * K + kc0))[c];
                } else {
                    pa[it] = pa[2 + it] = make_float4(0.f, 0.f, 0.f, 0.f);
                }
            }
        }
#pragma unroll
        for (int it = 0; it < 2; it++) {
            int idx = it * 256 + tid;
            int r = idx >> 2, c = idx & 3;
            int row = n0 + r;
            pb[it]     = ((const float4*)(Bhi + (size_t)row * K + kc0))[c];
            pb[2 + it] = ((const float4*)(Blo + (size_t)row * K + kc0))[c];
        }
    };

    auto store_chunk = [&]() {
        if (AFP32) {
#pragma unroll
            for (int it = 0; it < 4; it++) {
                int idx = it * 256 + tid;
                int r = idx >> 3, c = idx & 7;
                float4 v = pa[it];
                __nv_bfloat16 hx = __float2bfloat16(v.x), hy = __float2bfloat16(v.y);
                __nv_bfloat16 hz = __float2bfloat16(v.z), hw = __float2bfloat16(v.w);
                __nv_bfloat16* ph = &s[0][r * ST + c * 4];
                __nv_bfloat16* pl = &s[1][r * ST + c * 4];
                *(__nv_bfloat162*)(ph)     = __nv_bfloat162{hx, hy};
                *(__nv_bfloat162*)(ph + 2) = __nv_bfloat162{hz, hw};
                *(__nv_bfloat162*)(pl) = __nv_bfloat162{
                    __float2bfloat16(v.x - __bfloat162float(hx)),
                    __float2bfloat16(v.y - __bfloat162float(hy))};
                *(__nv_bfloat162*)(pl + 2) = __nv_bfloat162{
                    __float2bfloat16(v.z - __bfloat162float(hz)),
                    __float2bfloat16(v.w - __bfloat162float(hw))};
            }
        } else {
#pragma unroll
            for (int it = 0; it < 2; it++) {
                int idx = it * 256 + tid;
                int r = idx >> 2, c = idx & 3;
                *(float4*)&s[0][r * ST + c * 8] = pa[it];
                *(float4*)&s[1][r * ST + c * 8] = pa[2 + it];
            }
        }
#pragma unroll
        for (int it = 0; it < 2; it++) {
            int idx = it * 256 + tid;
            int r = idx >> 2, c = idx & 3;
            *(float4*)&s[2][r * ST + c * 8] = pb[it];
            *(float4*)&s[3][r * ST + c * 8] = pb[2 + it];
        }
    };

    load_chunk(0);
    for (int ch = 0; ch < CHUNKS; ch++) {
        store_chunk();
        __syncthreads();
        if (ch + 1 < CHUNKS) load_chunk((ch + 1) * 32);   // overlap with compute

#pragma unroll
        for (int ks = 0; ks < 2; ks++) {
            uint32_t ah[4][4], al[4][4], bh[2][4], bl[2][4];
#pragma unroll
            for (int mt = 0; mt < 4; mt++) {
                uint32_t off = ((a_row + mt * 16) * ST + ks * 16 + a_kof) * 2;
                ldmx4(ah[mt], smem_u32(&s[0][0]) + off);
                ldmx4(al[mt], smem_u32(&s[1][0]) + off);
            }
#pragma unroll
            for (int p = 0; p < 2; p++) {
                uint32_t off = ((b_row + p * 16) * ST + ks * 16 + b_kof) * 2;
                ldmx4(bh[p], smem_u32(&s[2][0]) + off);
                ldmx4(bl[p], smem_u32(&s[3][0]) + off);
            }
#pragma unroll
            for (int mt = 0; mt < 4; mt++)
#pragma unroll
                for (int nt = 0; nt < 4; nt++) {
                    int p = nt >> 1, q = (nt & 1) * 2;
                    mma16816(acc[mt][nt], ah[mt], bh[p][q], bh[p][q + 1]);
                    mma16816(acc[mt][nt], ah[mt], bl[p][q], bl[p][q + 1]);
                    mma16816(acc[mt][nt], al[mt], bh[p][q], bh[p][q + 1]);
                }
        }
        __syncthreads();
    }

    // ---- epilogue ----
#pragma unroll
    for (int mt = 0; mt < 4; mt++) {
        int row0 = m0 + wm + mt * 16 + (lane >> 2);
        int row1 = row0 + 8;
#pragma unroll
        for (int nt = 0; nt < 4; nt++) {
            int col = n0 + wn + nt * 8 + (lane & 3) * 2;
            if (row0 < NN)
                *(float2*)(C + (size_t)row0 * NT + col) =
                    make_float2(acc[mt][nt][0], acc[mt][nt][1]);
            if (row1 < NN)
                *(float2*)(C + (size_t)row1 * NT + col) =
                    make_float2(acc[mt][nt][2], acc[mt][nt][3]);
        }
    }
}

// ============================ fused CSR gather ============================
template <int C, bool SPLIT>
__global__ __launch_bounds__(256)
void k_gather(const float* __restrict__ h, const float* __restrict__ bias,
              float* __restrict__ outf, __nv_bfloat16* __restrict__ outhi,
              __nv_bfloat16* __restrict__ outlo) {
    constexpr int L = C / 4;
    constexpr int NPB = 256 / L;
    int node = blockIdx.x * NPB + threadIdx.x / L;
    if (node >= NN) return;
    int lane = threadIdx.x % L;

    const float4* h4 = (const float4*)h;
    float dd = g_dinv[node];
    float4 self = h4[(size_t)node * L + lane];
    float ws = dd * dd;
    float4 acc = make_float4(self.x * ws, self.y * ws, self.z * ws, self.w * ws);

    int e   = g_rowptr[node];
    int end = g_rowptr[node + 1];
    for (; e + 1 < end; e += 2) {                 // 2 independent chains (MLP)
        int s0 = __ldg(&g_esrc[e]);
        int s1 = __ldg(&g_esrc[e + 1]);
        float w0 = __ldg(&g_dinv[s0]) * dd;
        float w1 = __ldg(&g_dinv[s1]) * dd;
        float4 v0 = h4[(size_t)s0 * L + lane];
        float4 v1 = h4[(size_t)s1 * L + lane];
        acc.x = fmaf(v0.x, w0, fmaf(v1.x, w1, acc.x));
        acc.y = fmaf(v0.y, w0, fmaf(v1.y, w1, acc.y));
        acc.z = fmaf(v0.z, w0, fmaf(v1.z, w1, acc.z));
        acc.w = fmaf(v0.w, w0, fmaf(v1.w, w1, acc.w));
    }
    if (e < end) {
        int s0 = __ldg(&g_esrc[e]);
        float w0 = __ldg(&g_dinv[s0]) * dd;
        float4 v0 = h4[(size_t)s0 * L + lane];
        acc.x = fmaf(v0.x, w0, acc.x);
        acc.y = fmaf(v0.y, w0, acc.y);
        acc.z = fmaf(v0.z, w0, acc.z);
        acc.w = fmaf(v0.w, w0, acc.w);
    }

    float4 b = ((const float4*)bias)[lane];
    acc.x += b.x; acc.y += b.y; acc.z += b.z; acc.w += b.w;

    if (SPLIT) {
        acc.x = fmaxf(acc.x, 0.f); acc.y = fmaxf(acc.y, 0.f);
        acc.z = fmaxf(acc.z, 0.f); acc.w = fmaxf(acc.w, 0.f);
        __nv_bfloat16 hx = __float2bfloat16(acc.x), hy = __float2bfloat16(acc.y);
        __nv_bfloat16 hz = __float2bfloat16(acc.z), hw = __float2bfloat16(acc.w);
        size_t p2 = ((size_t)node * L + lane) * 2;
        ((__nv_bfloat162*)outhi)[p2]     = __nv_bfloat162{hx, hy};
        ((__nv_bfloat162*)outhi)[p2 + 1] = __nv_bfloat162{hz, hw};
        ((__nv_bfloat162*)outlo)[p2] = __nv_bfloat162{
            __float2bfloat16(acc.x - __bfloat162float(hx)),
            __float2bfloat16(acc.y - __bfloat162float(hy))};
        ((__nv_bfloat162*)outlo)[p2 + 1] = __nv_bfloat162{
            __float2bfloat16(acc.z - __bfloat162float(hz)),
            __float2bfloat16(acc.w - __bfloat162float(hw))};
    } else {
        ((float4*)outf)[(size_t)node * L + lane] = acc;
    }
}

// ============================ launch ============================
extern "C" void kernel_launch(void* const* d_in, const int* in_sizes, int n_in,
                              void* d_out, int out_size) {
    const float* x  = (const float*)d_in[0];
    const void*  ei = d_in[1];
    const float* W1 = (const float*)d_in[2];
    const float* b1 = (const float*)d_in[3];
    const float* W2 = (const float*)d_in[4];
    const float* b2 = (const float*)d_in[5];
    float*       out = (float*)d_out;

    float *h1, *h2;
    __nv_bfloat16 *aghi, *aglo, *w1hi, *w1lo, *w2hi, *w2lo;
    cudaGetSymbolAddress((void**)&h1, g_h1);
    cudaGetSymbolAddress((void**)&h2, g_h2);
    cudaGetSymbolAddress((void**)&aghi, g_aghi);
    cudaGetSymbolAddress((void**)&aglo, g_aglo);
    cudaGetSymbolAddress((void**)&w1hi, g_w1hi);
    cudaGetSymbolAddress((void**)&w1lo, g_w1lo);
    cudaGetSymbolAddress((void**)&w2hi, g_w2hi);
    cudaGetSymbolAddress((void**)&w2lo, g_w2lo);

    // dtype + CSR
    k_flag_init<<<1, 1>>>();
    k_detect<<<1, 256>>>((const unsigned int*)ei);
    k_zero_cnt<<<(NN + 255) / 256, 256>>>();
    k_count<<<(NE + 255) / 256, 256>>>(ei);
    k_dinv_from_cnt<<<(NN + 255) / 256, 256>>>();
    k_scan<<<1, 1024>>>();
    k_fill<<<(NE + 255) / 256, 256>>>(ei);

    // weight splits (x split is fused into GEMM1)
    k_splitT<<<(IN_CH * HID + 255) / 256, 256>>>(W1, w1hi, w1lo, IN_CH, HID);
    k_splitT<<<(HID * OUTC + 255) / 256, 256>>>(W2, w2hi, w2lo, HID, OUTC);

    const int NB = (NN + 127) / 128;   // 391

    // ---- layer 1 ----
    dim3 g1(NB, HID / 128);
    k_mma<IN_CH, HID, true><<<g1, 256>>>(x, nullptr, nullptr, w1hi, w1lo, h1);
    k_gather<HID, true><<<(NN + 3) / 4, 256>>>(h1, b1, nullptr, aghi, aglo);

    // ---- layer 2 ----
    dim3 g2(NB, OUTC / 128);
    k_mma<HID, OUTC, false><<<g2, 256>>>(nullptr, aghi, aglo, w2hi, w2lo, h2);
    k_gather<OUTC, false><<<(NN + 7) / 8, 256>>>(h2, b2, out, nullptr, nullptr);
}